// round 2
// baseline (speedup 1.0000x reference)
#include <cuda_runtime.h>
#include <cstdint>

#define FULL 0xffffffffu

constexpr int B = 8, H = 16, N = 8192, HD = 64, J = 20;
constexpr int HQ = HD / 4;  // 16 float4 per row
__device__ constexpr int OFF[J] = {1,2,3,4,5,6,7,8,9,11,13,15,16,23,32,64,128,256,512,1024};

constexpr float LOG2E = 1.4426950408889634f;
constexpr float DOTC  = 0.125f * LOG2E;   // 1/sqrt(64) * log2(e)

constexpr int PAIRS = 4;                  // pairs per warp (8 consecutive positions)
constexpr int WARPS = 8;
constexpr int POS_PER_BLOCK = WARPS * 2 * PAIRS;  // 64

__device__ __forceinline__ float ex2f(float x) {
    float y;
    asm("ex2.approx.ftz.f32 %0, %1;" : "=f"(y) : "f"(x));
    return y;
}

template<bool MASK>
__device__ __forceinline__ void process_pair(
    int n_me, int sub,
    const float4* __restrict__ qb, const float4* __restrict__ kb,
    const float4* __restrict__ vb, float4* __restrict__ ob,
    const float4* __restrict__ se_s, float pb0, float pb1)
{
    const float NEG = __int_as_float(0xff800000);  // -inf
    const int row = n_me * HQ + sub;
    const float4 q4 = qb[row];

    float part[32];
#pragma unroll
    for (int j = 0; j < J; j++) {
        const int d = OFF[j];
        float4 k4;
        bool ok = true;
        if (MASK) {
            int idx = n_me - d;
            ok = idx >= 0;
            int ci = ok ? idx : 0;
            k4 = kb[ci * HQ + sub];
        } else {
            k4 = kb[row - d * HQ];   // compile-time immediate byte offset
        }
        const float4 s4 = se_s[j * HQ + sub];
        float t = q4.x * (k4.x + s4.x);
        t = fmaf(q4.y, k4.y + s4.y, t);
        t = fmaf(q4.z, k4.z + s4.z, t);
        t = fmaf(q4.w, k4.w + s4.w, t);
        part[j] = (MASK && !ok) ? NEG : t;
    }
#pragma unroll
    for (int j = J; j < 32; j++) part[j] = NEG;

    // Transposed reduction across the 16-lane half: 32 values -> 2 per lane.
    // After this, lane `sub` holds full sums for j = 2*sub (part[0]) and
    // j = 2*sub + 1 (part[1]).
#pragma unroll
    for (int s = 8; s >= 1; s >>= 1) {
        const int c2 = 2 * s;  // half of current value count
        const bool upper = (sub & s) != 0;
#pragma unroll
        for (int vv = 0; vv < c2; vv++) {
            float a = part[vv], b = part[vv + c2];
            float send = upper ? a : b;
            float recv = __shfl_xor_sync(FULL, send, s);
            part[vv] = (upper ? b : a) + recv;
        }
    }

    float s0 = fmaf(part[0], DOTC, pb0);   // log2-domain scores
    float s1 = fmaf(part[1], DOTC, pb1);

    float m = fmaxf(s0, s1);
#pragma unroll
    for (int s = 8; s >= 1; s >>= 1)
        m = fmaxf(m, __shfl_xor_sync(FULL, m, s));
    m = fmaxf(m, -1e30f);  // guard all-masked row (n=0)

    float e0 = ex2f(s0 - m);
    float e1 = ex2f(s1 - m);
    float den = e0 + e1;
#pragma unroll
    for (int s = 8; s >= 1; s >>= 1)
        den += __shfl_xor_sync(FULL, den, s);
    float r = __fdividef(1.0f, fmaxf(den, 1e-30f));
    float p0 = e0 * r, p1 = e1 * r;

    float4 acc = make_float4(0.f, 0.f, 0.f, 0.f);
#pragma unroll
    for (int j = 0; j < J; j++) {
        const int d = OFF[j];
        float pj = __shfl_sync(FULL, (j & 1) ? p1 : p0, j >> 1, 16);
        float4 v4;
        if (MASK) {
            int idx = n_me - d;
            int ci = idx >= 0 ? idx : 0;
            v4 = vb[ci * HQ + sub];   // pj == 0 when masked
        } else {
            v4 = vb[row - d * HQ];
        }
        acc.x = fmaf(pj, v4.x, acc.x);
        acc.y = fmaf(pj, v4.y, acc.y);
        acc.z = fmaf(pj, v4.z, acc.z);
        acc.w = fmaf(pj, v4.w, acc.w);
    }
    ob[row] = acc;
}

__global__ __launch_bounds__(256, 2)
void dsqg_kernel(const float* __restrict__ q, const float* __restrict__ k,
                 const float* __restrict__ v, const float* __restrict__ pb,
                 const float* __restrict__ se, float* __restrict__ out)
{
    __shared__ float4 se_s[J * HQ];
    for (int i = threadIdx.x; i < J * HQ; i += blockDim.x)
        se_s[i] = reinterpret_cast<const float4*>(se)[i];
    __syncthreads();

    const int bh   = blockIdx.y;
    const int h    = bh & (H - 1);
    const int warp = threadIdx.x >> 5;
    const int lane = threadIdx.x & 31;
    const int sub  = lane & 15;
    const int half = lane >> 4;

    const size_t base = (size_t)bh * N * HQ;
    const float4* qb = reinterpret_cast<const float4*>(q) + base;
    const float4* kb = reinterpret_cast<const float4*>(k) + base;
    const float4* vb = reinterpret_cast<const float4*>(v) + base;
    float4*       ob = reinterpret_cast<float4*>(out) + base;

    float pb0 = 0.f, pb1 = 0.f;
    if (sub < J / 2) {   // sub < 10: owns j = 2*sub, 2*sub+1
        pb0 = pb[(2 * sub) * H + h] * LOG2E;
        pb1 = pb[(2 * sub + 1) * H + h] * LOG2E;
    }

    const int base_n = blockIdx.x * POS_PER_BLOCK + warp * (2 * PAIRS);
    if (base_n >= 1024) {
#pragma unroll
        for (int p = 0; p < PAIRS; p++)
            process_pair<false>(base_n + 2 * p + half, sub, qb, kb, vb, ob,
                                se_s, pb0, pb1);
    } else {
        for (int p = 0; p < PAIRS; p++)
            process_pair<true>(base_n + 2 * p + half, sub, qb, kb, vb, ob,
                               se_s, pb0, pb1);
    }
}

extern "C" void kernel_launch(void* const* d_in, const int* in_sizes, int n_in,
                              void* d_out, int out_size) {
    const float* q  = (const float*)d_in[0];
    const float* k  = (const float*)d_in[1];
    const float* v  = (const float*)d_in[2];
    const float* pb = (const float*)d_in[3];
    const float* se = (const float*)d_in[4];
    dim3 grid(N / POS_PER_BLOCK, B * H);
    dsqg_kernel<<<grid, 256>>>(q, k, v, pb, se, (float*)d_out);
}